// round 3
// baseline (speedup 1.0000x reference)
#include <cuda_runtime.h>
#include <math.h>
#include <stdint.h>

#define NCHUNK 16

// ---------------- scratch (floats) ----------------
#define OFF_W1   ((size_t)0)
#define OFF_W2   ((size_t)524288)
#define OFF_S1   ((size_t)1048576)
#define OFF_S2   ((size_t)1572864)
#define OFF_HG   ((size_t)2097152)
#define OFF_GP   ((size_t)3145728)
#define OFF_DH   ((size_t)4194304)
#define OFF_DP   ((size_t)5242880)
#define OFF_KALL ((size_t)5767168)
#define OFF_VALL ((size_t)14155776)
#define OFF_Q    ((size_t)22544384)
#define OFF_HQ   ((size_t)30932992)
#define SCRATCH_TOTAL ((size_t)47710208)

__device__ __align__(1024) float g_scratch[SCRATCH_TOTAL];

// ---------------- math ----------------
__device__ __forceinline__ float geluf(float x) {
    return 0.5f * x * (1.0f + erff(x * 0.7071067811865476f));
}
__device__ __forceinline__ float gelugrad(float x) {
    float cdf = 0.5f * (1.0f + erff(x * 0.7071067811865476f));
    float pdf = 0.3989422804014327f * expf(-0.5f * x * x);
    return cdf + x * pdf;
}
__device__ __forceinline__ float sigm(float t) { return 1.0f / (1.0f + expf(-t)); }

__device__ __forceinline__ int maprow(int r) {
    // x row r (b*4096 + t) -> chunk-major row: chunk*1024 + b*256 + s
    return ((r & 4095) >> 8) * 1024 + (r >> 12) * 256 + (r & 255);
}

__device__ __forceinline__ float tf32r(float x) {
    uint32_t r;
    asm("cvt.rna.tf32.f32 %0, %1;" : "=r"(r) : "f"(x));
    return __uint_as_float(r);
}

__device__ __forceinline__ void mma8(float* c, const uint32_t* a, const uint32_t* b) {
    asm volatile(
        "mma.sync.aligned.m16n8k8.row.col.f32.tf32.tf32.f32 "
        "{%0,%1,%2,%3}, {%4,%5,%6,%7}, {%8,%9}, {%0,%1,%2,%3};"
        : "+f"(c[0]), "+f"(c[1]), "+f"(c[2]), "+f"(c[3])
        : "r"(a[0]), "r"(a[1]), "r"(a[2]), "r"(a[3]), "r"(b[0]), "r"(b[1]));
}

enum { EPI_NONE = 0, EPI_GELU_BOTH, EPI_GELU, EPI_DPRED, EPI_MULGP, EPI_UPDATE };

struct Z3P { const float* B0; const float* B1; const float* B2;
             float* C0; float* C1; float* C2; };

// Fragment-order smem layout (per buffer):
//   A: [mblk(8)][s(2)][lane(32)][reg(4)]  = 2048 floats
//   B: [nblk(16)][s(2)][lane(32)][reg(2)] = 2048 floats
// mma m16n8k8 tf32 fragments:
//   a0=(r=l>>2,   c=l&3)  a1=(r+8, c)  a2=(r, c+4)  a3=(r+8, c+4)
//   b0=(k=l&3, n=l>>2)    b1=(k+4, n)
//   c0=(r=l>>2, c=2(l&3)) c1=(r,c+1)   c2=(r+8,c)   c3=(r+8,c+1)

template <int TRA, int TRB, int EPI, int Z3>
__global__ __launch_bounds__(256) void mgemm(
    const float* __restrict__ A, const float* __restrict__ B,
    float* __restrict__ C, float* __restrict__ C2,
    const float* __restrict__ aux, float* __restrict__ S,
    const float* __restrict__ sa, const float* __restrict__ sl,
    const float* __restrict__ sd, const int* __restrict__ su,
    int M, int N, int K, int ldA, int ldB, int outmap, Z3P z3)
{
    __shared__ float Asm[2][2048];
    __shared__ float Bsm[2][2048];

    const int tid = threadIdx.x;
    const int lane = tid & 31;
    const int wid = tid >> 5;
    const int wr = wid >> 1;     // 0..3 warp row
    const int wc = wid & 1;      // 0..1 warp col
    const int row0 = blockIdx.y * 128;
    const int col0 = blockIdx.x * 128;

    if (Z3) {
        int z = blockIdx.z;
        B = (z == 0) ? z3.B0 : (z == 1) ? z3.B1 : z3.B2;
        C = (z == 0) ? z3.C0 : (z == 1) ? z3.C1 : z3.C2;
        outmap = (z < 2);
    }

    float acc[2][8][4];
#pragma unroll
    for (int i = 0; i < 2; i++)
#pragma unroll
        for (int j = 0; j < 8; j++)
#pragma unroll
            for (int q = 0; q < 4; q++) acc[i][j][q] = 0.0f;

    const int NC = K >> 4;
    float4 ra[2], rb[2];

    // ---- prefetch chunk 0 ----
    {
        const int k0 = 0;
#pragma unroll
        for (int i = 0; i < 2; i++) {
            int idx = tid + i * 256;
            if (!TRA) {
                int m = idx >> 2, k4 = idx & 3;
                ra[i] = *(const float4*)(A + (size_t)(row0 + m) * ldA + k0 + k4 * 4);
            } else {
                int kk = idx >> 5, m4 = idx & 31;
                ra[i] = *(const float4*)(A + (size_t)(k0 + kk) * ldA + row0 + m4 * 4);
            }
            if (!TRB) {
                int kk = idx >> 5, n4 = idx & 31;
                rb[i] = *(const float4*)(B + (size_t)(k0 + kk) * ldB + col0 + n4 * 4);
            } else {
                int n = idx >> 2, k4 = idx & 3;
                rb[i] = *(const float4*)(B + (size_t)(col0 + n) * ldB + k0 + k4 * 4);
            }
        }
    }

    for (int c = 0; c < NC; c++) {
        const int buf = c & 1;
        // ---- store staged regs into smem (fragment order, tf32-rounded) ----
#pragma unroll
        for (int i = 0; i < 2; i++) {
            int idx = tid + i * 256;
            float va[4] = {ra[i].x, ra[i].y, ra[i].z, ra[i].w};
            float vb[4] = {rb[i].x, rb[i].y, rb[i].z, rb[i].w};
            // A
            if (!TRA) {
                int m = idx >> 2, k4 = idx & 3;
                int mblk = m >> 4, r = m & 15;
#pragma unroll
                for (int j = 0; j < 4; j++) {
                    int kk = k4 * 4 + j;
                    int s = kk >> 3, kl = kk & 7;
                    int t = (r & 7) * 4 + (kl & 3);
                    int rg = (r >= 8 ? 1 : 0) + (kl >= 4 ? 2 : 0);
                    Asm[buf][((mblk * 2 + s) * 32 + t) * 4 + rg] = tf32r(va[j]);
                }
            } else {
                int kk = idx >> 5, m4 = idx & 31;
                int s = kk >> 3, kl = kk & 7;
#pragma unroll
                for (int j = 0; j < 4; j++) {
                    int m = m4 * 4 + j;
                    int mblk = m >> 4, r = m & 15;
                    int t = (r & 7) * 4 + (kl & 3);
                    int rg = (r >= 8 ? 1 : 0) + (kl >= 4 ? 2 : 0);
                    Asm[buf][((mblk * 2 + s) * 32 + t) * 4 + rg] = tf32r(va[j]);
                }
            }
            // B
            if (!TRB) {
                int kk = idx >> 5, n4 = idx & 31;
                int s = kk >> 3, kl = kk & 7;
#pragma unroll
                for (int j = 0; j < 4; j++) {
                    int n = n4 * 4 + j;
                    int nblk = n >> 3;
                    int t = (n & 7) * 4 + (kl & 3);
                    int rg = (kl >= 4 ? 1 : 0);
                    Bsm[buf][((nblk * 2 + s) * 32 + t) * 2 + rg] = tf32r(vb[j]);
                }
            } else {
                int n = idx >> 2, k4 = idx & 3;
                int nblk = n >> 3;
#pragma unroll
                for (int j = 0; j < 4; j++) {
                    int kk = k4 * 4 + j;
                    int s = kk >> 3, kl = kk & 7;
                    int t = (n & 7) * 4 + (kl & 3);
                    int rg = (kl >= 4 ? 1 : 0);
                    Bsm[buf][((nblk * 2 + s) * 32 + t) * 2 + rg] = tf32r(vb[j]);
                }
            }
        }
        __syncthreads();

        // ---- prefetch next chunk ----
        if (c + 1 < NC) {
            const int k0 = (c + 1) * 16;
#pragma unroll
            for (int i = 0; i < 2; i++) {
                int idx = tid + i * 256;
                if (!TRA) {
                    int m = idx >> 2, k4 = idx & 3;
                    ra[i] = *(const float4*)(A + (size_t)(row0 + m) * ldA + k0 + k4 * 4);
                } else {
                    int kk = idx >> 5, m4 = idx & 31;
                    ra[i] = *(const float4*)(A + (size_t)(k0 + kk) * ldA + row0 + m4 * 4);
                }
                if (!TRB) {
                    int kk = idx >> 5, n4 = idx & 31;
                    rb[i] = *(const float4*)(B + (size_t)(k0 + kk) * ldB + col0 + n4 * 4);
                } else {
                    int n = idx >> 2, k4 = idx & 3;
                    rb[i] = *(const float4*)(B + (size_t)(col0 + n) * ldB + k0 + k4 * 4);
                }
            }
        }

        // ---- compute from buf ----
#pragma unroll
        for (int s = 0; s < 2; s++) {
            uint32_t af[2][4];
#pragma unroll
            for (int mi = 0; mi < 2; mi++) {
                float4 t4 = *(const float4*)&Asm[buf][(((wr * 2 + mi) * 2 + s) * 32 + lane) * 4];
                af[mi][0] = __float_as_uint(t4.x); af[mi][1] = __float_as_uint(t4.y);
                af[mi][2] = __float_as_uint(t4.z); af[mi][3] = __float_as_uint(t4.w);
            }
#pragma unroll
            for (int nj = 0; nj < 8; nj++) {
                float2 t2 = *(const float2*)&Bsm[buf][(((wc * 8 + nj) * 2 + s) * 32 + lane) * 2];
                uint32_t bf[2] = {__float_as_uint(t2.x), __float_as_uint(t2.y)};
                mma8(acc[0][nj], af[0], bf);
                mma8(acc[1][nj], af[1], bf);
            }
        }
        __syncthreads();
    }

    // ---------------- epilogue ----------------
    float al = 0.f, lrv = 0.f, dc = 0.f;
    int um = 1;
    if (EPI == EPI_UPDATE) {
        al = sigm(sa[0]); lrv = sigm(sl[0]); dc = sigm(sd[0]); um = su[0];
        if (!um) return;
    }

#pragma unroll
    for (int mi = 0; mi < 2; mi++) {
#pragma unroll
        for (int half = 0; half < 2; half++) {
            int r = row0 + (wr * 2 + mi) * 16 + (lane >> 2) + half * 8;
#pragma unroll
            for (int nj = 0; nj < 8; nj++) {
                int cl = col0 + (wc * 8 + nj) * 8 + 2 * (lane & 3);
                float v0 = acc[mi][nj][half * 2 + 0];
                float v1 = acc[mi][nj][half * 2 + 1];
                size_t idx = (size_t)r * N + cl;
                if (EPI == EPI_NONE) {
                    size_t orow = outmap ? (size_t)maprow(r) : (size_t)r;
                    float2 o = {v0, v1};
                    *(float2*)&C[orow * N + cl] = o;
                } else if (EPI == EPI_GELU_BOTH) {
                    float2 o = {geluf(v0), geluf(v1)};
                    float2 g = {gelugrad(v0), gelugrad(v1)};
                    *(float2*)&C[idx] = o;
                    *(float2*)&C2[idx] = g;
                } else if (EPI == EPI_GELU) {
                    float2 o = {geluf(v0), geluf(v1)};
                    *(float2*)&C[idx] = o;
                } else if (EPI == EPI_DPRED) {
                    float2 a2 = *(const float2*)&aux[idx];
                    float2 o = {(v0 - a2.x) * 3.814697265625e-06f,
                                (v1 - a2.y) * 3.814697265625e-06f};
                    *(float2*)&C[idx] = o;
                } else if (EPI == EPI_MULGP) {
                    float2 g = *(const float2*)&aux[idx];
                    float2 o = {v0 * g.x, v1 * g.y};
                    *(float2*)&C[idx] = o;
                } else {  // EPI_UPDATE
                    float2 sv = *(float2*)&S[idx];
                    float2 wv = *(float2*)&C[idx];
                    sv.x = dc * sv.x - lrv * v0;
                    sv.y = dc * sv.y - lrv * v1;
                    wv.x = (1.0f - al) * wv.x + sv.x;
                    wv.y = (1.0f - al) * wv.y + sv.y;
                    *(float2*)&S[idx] = sv;
                    *(float2*)&C[idx] = wv;
                }
            }
        }
    }
}

__global__ void init_kernel(const float* __restrict__ w1, const float* __restrict__ w2,
                            float* __restrict__ W1, float* __restrict__ W2,
                            float* __restrict__ S1, float* __restrict__ S2)
{
    int i = blockIdx.x * blockDim.x + threadIdx.x;
    if (i < 524288) {
        W1[i] = w1[i]; S1[i] = 0.0f;
        W2[i] = w2[i]; S2[i] = 0.0f;
    }
}

extern "C" void kernel_launch(void* const* d_in, const int* in_sizes, int n_in,
                              void* d_out, int out_size)
{
    const float* x       = (const float*)d_in[0];
    const float* w_q     = (const float*)d_in[1];
    const float* w_k     = (const float*)d_in[2];
    const float* w_v     = (const float*)d_in[3];
    const float* mem_w1  = (const float*)d_in[4];
    const float* mem_w2  = (const float*)d_in[5];
    const float* alpha_t = (const float*)d_in[6];
    const float* lr_t    = (const float*)d_in[7];
    const float* decay_t = (const float*)d_in[8];
    const int*   upd     = (const int*)d_in[9];
    float* out = (float*)d_out;

    float* sc = nullptr;
    cudaGetSymbolAddress((void**)&sc, g_scratch);
    float* W1 = sc + OFF_W1;   float* W2 = sc + OFF_W2;
    float* S1 = sc + OFF_S1;   float* S2 = sc + OFF_S2;
    float* HG = sc + OFF_HG;   float* GP = sc + OFF_GP;
    float* DH = sc + OFF_DH;   float* DP = sc + OFF_DP;
    float* KA = sc + OFF_KALL; float* VA = sc + OFF_VALL;
    float* Q  = sc + OFF_Q;    float* HQ = sc + OFF_HQ;

    init_kernel<<<2048, 256>>>(mem_w1, mem_w2, W1, W2, S1, S2);

    Z3P z3 = { w_k, w_v, w_q, KA, VA, Q };
    Z3P z0 = { nullptr, nullptr, nullptr, nullptr, nullptr, nullptr };

    // K_all / V_all (chunk-major) + Q: one launch, grid.z = 3
    mgemm<0,0,EPI_NONE,1><<<dim3(4, 128, 3), 256>>>(
        x, nullptr, nullptr, nullptr, nullptr, nullptr,
        nullptr, nullptr, nullptr, nullptr,
        16384, 512, 512, 512, 512, 0, z3);

    for (int c = 0; c < NCHUNK; c++) {
        float* Kc = KA + (size_t)c * 524288;
        float* Vc = VA + (size_t)c * 524288;
        // h = Kc @ W1 ; HG = gelu(h), GP = gelu'(h)   [1024,1024,512]
        mgemm<0,0,EPI_GELU_BOTH,0><<<dim3(8, 8), 256>>>(
            Kc, W1, HG, GP, nullptr, nullptr, nullptr, nullptr, nullptr, nullptr,
            1024, 1024, 512, 512, 1024, 0, z0);
        // dpred = (HG @ W2 - Vc) * 2/Nel   [1024,512,1024]
        mgemm<0,0,EPI_DPRED,0><<<dim3(4, 8), 256>>>(
            HG, W2, DP, nullptr, Vc, nullptr, nullptr, nullptr, nullptr, nullptr,
            1024, 512, 1024, 1024, 512, 0, z0);
        // dh = (DP @ W2^T) * GP   [1024,1024,512]  (B stored [N=1024, K=512])
        mgemm<0,1,EPI_MULGP,0><<<dim3(8, 8), 256>>>(
            DP, W2, DH, nullptr, GP, nullptr, nullptr, nullptr, nullptr, nullptr,
            1024, 1024, 512, 512, 512, 0, z0);
        // g2 = HG^T @ DP -> update W2/S2   [1024,512], K=1024
        mgemm<1,0,EPI_UPDATE,0><<<dim3(4, 8), 256>>>(
            HG, DP, W2, nullptr, nullptr, S2, alpha_t, lr_t, decay_t, upd,
            1024, 512, 1024, 1024, 512, 0, z0);
        // g1 = Kc^T @ DH -> update W1/S1   [512,1024], K=1024
        mgemm<1,0,EPI_UPDATE,0><<<dim3(8, 4), 256>>>(
            Kc, DH, W1, nullptr, nullptr, S1, alpha_t, lr_t, decay_t, upd,
            512, 1024, 1024, 512, 1024, 0, z0);
    }

    // hq = gelu(Q @ W1)   [16384,1024,512]
    mgemm<0,0,EPI_GELU,0><<<dim3(8, 128), 256>>>(
        Q, W1, HQ, nullptr, nullptr, nullptr, nullptr, nullptr, nullptr, nullptr,
        16384, 1024, 512, 512, 1024, 0, z0);
    // out = HQ @ W2   [16384,512,1024]
    mgemm<0,0,EPI_NONE,0><<<dim3(4, 128), 256>>>(
        HQ, W2, out, nullptr, nullptr, nullptr, nullptr, nullptr, nullptr, nullptr,
        16384, 512, 1024, 1024, 512, 0, z0);
}

// round 4
// speedup vs baseline: 5.4356x; 5.4356x over previous
#include <cuda_runtime.h>
#include <math.h>
#include <stdint.h>

#define NCHUNK 16

// ---------------- scratch (floats) ----------------
#define OFF_W1   ((size_t)0)
#define OFF_W2   ((size_t)524288)
#define OFF_W1R  ((size_t)1048576)
#define OFF_W2R  ((size_t)1572864)
#define OFF_S1   ((size_t)2097152)
#define OFF_S2   ((size_t)2621440)
#define OFF_HG   ((size_t)3145728)
#define OFF_GP   ((size_t)4194304)
#define OFF_DH   ((size_t)5242880)
#define OFF_DP   ((size_t)6291456)
#define OFF_KA   ((size_t)6815744)
#define OFF_VA   ((size_t)15204352)
#define OFF_Q    ((size_t)23592960)
#define OFF_HQ   ((size_t)31981568)
#define OFF_XR   ((size_t)48758784)
#define OFF_WQR  ((size_t)57147392)
#define OFF_WKR  ((size_t)57409536)
#define OFF_WVR  ((size_t)57671680)
#define SCRATCH_TOTAL ((size_t)57933824)

__device__ __align__(1024) float g_scratch[SCRATCH_TOTAL];

// ---------------- helpers ----------------
__device__ __forceinline__ float geluf(float x) {
    return 0.5f * x * (1.0f + erff(x * 0.7071067811865476f));
}
__device__ __forceinline__ float gelugrad(float x) {
    float cdf = 0.5f * (1.0f + erff(x * 0.7071067811865476f));
    float pdf = 0.3989422804014327f * expf(-0.5f * x * x);
    return cdf + x * pdf;
}
__device__ __forceinline__ float sigm(float t) { return 1.0f / (1.0f + expf(-t)); }
__device__ __forceinline__ float tf32r(float x) {
    uint32_t r;
    asm("cvt.rna.tf32.f32 %0, %1;" : "=r"(r) : "f"(x));
    return __uint_as_float(r);
}
__device__ __forceinline__ int maprow(int r) {
    return ((r & 4095) >> 8) * 1024 + (r >> 12) * 256 + (r & 255);
}
__device__ __forceinline__ uint32_t smem_u32(const void* p) {
    uint32_t a;
    asm("{ .reg .u64 t; cvta.to.shared.u64 t, %1; cvt.u32.u64 %0, t; }" : "=r"(a) : "l"(p));
    return a;
}

#define CP16(dst, src) \
    asm volatile("cp.async.cg.shared.global [%0], [%1], 16;" :: "r"(dst), "l"(src))
#define CP_COMMIT() asm volatile("cp.async.commit_group;")
#define CP_WAIT1()  asm volatile("cp.async.wait_group 1;")

__device__ __forceinline__ void mma8(float* c, const uint32_t* a, const uint32_t* b) {
    asm volatile(
        "mma.sync.aligned.m16n8k8.row.col.f32.tf32.tf32.f32 "
        "{%0,%1,%2,%3}, {%4,%5,%6,%7}, {%8,%9}, {%0,%1,%2,%3};"
        : "+f"(c[0]), "+f"(c[1]), "+f"(c[2]), "+f"(c[3])
        : "r"(a[0]), "r"(a[1]), "r"(a[2]), "r"(a[3]), "r"(b[0]), "r"(b[1]));
}

// swizzled smem offsets (floats).  normal: tile[row][32k], trans: tile[32k][64rows]
__device__ __forceinline__ int aoff(int m, int k) { return m * 32 + (k ^ ((m & 7) * 4)); }
__device__ __forceinline__ int toff(int m, int k) { return k * 64 + (m ^ ((k & 3) * 8)); }

enum { EPI_NONE = 0, EPI_GELU_BOTH, EPI_GELU, EPI_DPRED, EPI_MULGP, EPI_UPDATE };

struct Z3P { const float* B0; const float* B1; const float* B2;
             float* C0; float* C1; float* C2; };

#define STAGES 3
#define STAGE_F 4096  /* floats per stage: A 2048 + B 2048 */

template <int TRA, int TRB>
__device__ __forceinline__ void load_stage(
    uint32_t sA, uint32_t sB, const float* A, const float* B,
    int row0, int col0, int k0, int ldA, int ldB, int tid)
{
#pragma unroll
    for (int q = 0; q < 4; q++) {
        int idx = tid + q * 128;
        if (!TRA) {
            int m = idx >> 3, k4 = idx & 7;
            const float* src = A + (size_t)(row0 + m) * ldA + k0 + k4 * 4;
            CP16(sA + 4u * (uint32_t)(m * 32 + ((k4 * 4) ^ ((m & 7) * 4))), src);
        } else {
            int kk = idx >> 4, m4 = idx & 15;
            const float* src = A + (size_t)(k0 + kk) * ldA + row0 + m4 * 4;
            CP16(sA + 4u * (uint32_t)(kk * 64 + ((m4 * 4) ^ ((kk & 3) * 8))), src);
        }
    }
#pragma unroll
    for (int q = 0; q < 4; q++) {
        int idx = tid + q * 128;
        if (TRB) {
            int n = idx >> 3, k4 = idx & 7;
            const float* src = B + (size_t)(col0 + n) * ldB + k0 + k4 * 4;
            CP16(sB + 4u * (uint32_t)(n * 32 + ((k4 * 4) ^ ((n & 7) * 4))), src);
        } else {
            int kk = idx >> 4, n4 = idx & 15;
            const float* src = B + (size_t)(k0 + kk) * ldB + col0 + n4 * 4;
            CP16(sB + 4u * (uint32_t)(kk * 64 + ((n4 * 4) ^ ((kk & 3) * 8))), src);
        }
    }
}

// BM=BN=64, BK=32, 128 threads (4 warps 2x2), warp tile 32x32 (2 x m16, 4 x n8)
template <int TRA, int TRB, int EPI, int Z3>
__global__ __launch_bounds__(128) void mgemm(
    const float* __restrict__ A, const float* __restrict__ B,
    float* __restrict__ C, float* __restrict__ C2, float* __restrict__ Cr,
    const float* __restrict__ aux, float* __restrict__ S,
    const float* __restrict__ sa, const float* __restrict__ sl,
    const float* __restrict__ sd, const int* __restrict__ su,
    int N, int K, int ldA, int ldB, int outmap, Z3P z3)
{
    extern __shared__ float smf[];
    const int tid = threadIdx.x;
    const int lane = tid & 31;
    const int wid = tid >> 5;
    const int wr = wid >> 1, wc = wid & 1;
    const int row0 = blockIdx.y * 64, col0 = blockIdx.x * 64;
    int rnd = 0;

    if (Z3) {
        int z = blockIdx.z;
        B = (z == 0) ? z3.B0 : (z == 1) ? z3.B1 : z3.B2;
        C = (z == 0) ? z3.C0 : (z == 1) ? z3.C1 : z3.C2;
        outmap = (z < 2);
        rnd = (z != 1);
    }

    const uint32_t sbase = smem_u32(smf);
    const int NC = K >> 5;

    float acc[2][4][4];
#pragma unroll
    for (int i = 0; i < 2; i++)
#pragma unroll
        for (int j = 0; j < 4; j++)
#pragma unroll
            for (int q = 0; q < 4; q++) acc[i][j][q] = 0.0f;

    // prologue: stages 0,1
#pragma unroll
    for (int p = 0; p < 2; p++) {
        uint32_t sA = sbase + p * (STAGE_F * 4);
        load_stage<TRA, TRB>(sA, sA + 8192, A, B, row0, col0, p * 32, ldA, ldB, tid);
        CP_COMMIT();
    }

    const int lr = lane >> 2, lc = lane & 3;

    for (int c = 0; c < NC; c++) {
        CP_WAIT1();
        __syncthreads();
        // issue stage c+2
        if (c + 2 < NC) {
            uint32_t sA = sbase + ((c + 2) % STAGES) * (STAGE_F * 4);
            load_stage<TRA, TRB>(sA, sA + 8192, A, B, row0, col0, (c + 2) * 32, ldA, ldB, tid);
        }
        CP_COMMIT();

        const float* As = smf + (c % STAGES) * STAGE_F;
        const float* Bs = As + 2048;
#pragma unroll
        for (int s = 0; s < 4; s++) {
            const int k = s * 8 + lc;
            uint32_t af[2][4];
#pragma unroll
            for (int mi = 0; mi < 2; mi++) {
                int m = wr * 32 + mi * 16 + lr;
                if (!TRA) {
                    af[mi][0] = __float_as_uint(As[aoff(m,     k)]);
                    af[mi][1] = __float_as_uint(As[aoff(m + 8, k)]);
                    af[mi][2] = __float_as_uint(As[aoff(m,     k + 4)]);
                    af[mi][3] = __float_as_uint(As[aoff(m + 8, k + 4)]);
                } else {
                    af[mi][0] = __float_as_uint(As[toff(m,     k)]);
                    af[mi][1] = __float_as_uint(As[toff(m + 8, k)]);
                    af[mi][2] = __float_as_uint(As[toff(m,     k + 4)]);
                    af[mi][3] = __float_as_uint(As[toff(m + 8, k + 4)]);
                }
            }
#pragma unroll
            for (int nj = 0; nj < 4; nj++) {
                int n = wc * 32 + nj * 8 + lr;
                uint32_t bf[2];
                if (TRB) {
                    bf[0] = __float_as_uint(Bs[aoff(n, k)]);
                    bf[1] = __float_as_uint(Bs[aoff(n, k + 4)]);
                } else {
                    bf[0] = __float_as_uint(Bs[toff(n, k)]);
                    bf[1] = __float_as_uint(Bs[toff(n, k + 4)]);
                }
                mma8(acc[0][nj], af[0], bf);
                mma8(acc[1][nj], af[1], bf);
            }
        }
        __syncthreads();
    }

    // ---------------- epilogue ----------------
    float al = 0.f, lrv = 0.f, dc = 0.f;
    if (EPI == EPI_UPDATE) {
        if (!su[0]) return;
        al = sigm(sa[0]); lrv = sigm(sl[0]); dc = sigm(sd[0]);
    }

#pragma unroll
    for (int mi = 0; mi < 2; mi++) {
#pragma unroll
        for (int nj = 0; nj < 4; nj++) {
#pragma unroll
            for (int half = 0; half < 2; half++) {
                int r = row0 + wr * 32 + mi * 16 + lr + half * 8;
                int cl = col0 + wc * 32 + nj * 8 + 2 * lc;
                float v0 = acc[mi][nj][half * 2 + 0];
                float v1 = acc[mi][nj][half * 2 + 1];
                size_t idx = (size_t)r * N + cl;
                if (EPI == EPI_NONE) {
                    size_t orow = outmap ? (size_t)maprow(r) : (size_t)r;
                    float2 o;
                    o.x = rnd ? tf32r(v0) : v0;
                    o.y = rnd ? tf32r(v1) : v1;
                    *(float2*)&C[orow * N + cl] = o;
                } else if (EPI == EPI_GELU_BOTH) {
                    float g0 = geluf(v0), g1 = geluf(v1);
                    float2 o = {tf32r(g0), tf32r(g1)};
                    float2 g = {gelugrad(v0), gelugrad(v1)};
                    *(float2*)&C[idx] = o;
                    *(float2*)&C2[idx] = g;
                } else if (EPI == EPI_GELU) {
                    float2 o = {tf32r(geluf(v0)), tf32r(geluf(v1))};
                    *(float2*)&C[idx] = o;
                } else if (EPI == EPI_DPRED) {
                    float2 a2 = *(const float2*)&aux[idx];
                    float2 o = {tf32r((v0 - a2.x) * 3.814697265625e-06f),
                                tf32r((v1 - a2.y) * 3.814697265625e-06f)};
                    *(float2*)&C[idx] = o;
                } else if (EPI == EPI_MULGP) {
                    float2 g = *(const float2*)&aux[idx];
                    float2 o = {tf32r(v0 * g.x), tf32r(v1 * g.y)};
                    *(float2*)&C[idx] = o;
                } else {  // EPI_UPDATE
                    float2 sv = *(float2*)&S[idx];
                    float2 wv = *(float2*)&C[idx];
                    sv.x = dc * sv.x - lrv * v0;
                    sv.y = dc * sv.y - lrv * v1;
                    wv.x = (1.0f - al) * wv.x + sv.x;
                    wv.y = (1.0f - al) * wv.y + sv.y;
                    *(float2*)&S[idx] = sv;
                    *(float2*)&C[idx] = wv;
                    float2 rv = {tf32r(wv.x), tf32r(wv.y)};
                    *(float2*)&Cr[idx] = rv;
                }
            }
        }
    }
}

__global__ void round_copy(const float4* __restrict__ src, float4* __restrict__ dst, int n4) {
    int i = blockIdx.x * blockDim.x + threadIdx.x;
    if (i < n4) {
        float4 v = src[i];
        v.x = tf32r(v.x); v.y = tf32r(v.y); v.z = tf32r(v.z); v.w = tf32r(v.w);
        dst[i] = v;
    }
}

__global__ void init_w(const float* __restrict__ w1, const float* __restrict__ w2,
                       float* __restrict__ W1, float* __restrict__ W1R, float* __restrict__ S1,
                       float* __restrict__ W2, float* __restrict__ W2R, float* __restrict__ S2)
{
    int i = blockIdx.x * blockDim.x + threadIdx.x;
    if (i < 524288) {
        float a = w1[i], b = w2[i];
        W1[i] = a; W1R[i] = tf32r(a); S1[i] = 0.0f;
        W2[i] = b; W2R[i] = tf32r(b); S2[i] = 0.0f;
    }
}

#define SMEMSZ (STAGES * STAGE_F * 4)

extern "C" void kernel_launch(void* const* d_in, const int* in_sizes, int n_in,
                              void* d_out, int out_size)
{
    const float* x       = (const float*)d_in[0];
    const float* w_q     = (const float*)d_in[1];
    const float* w_k     = (const float*)d_in[2];
    const float* w_v     = (const float*)d_in[3];
    const float* mem_w1  = (const float*)d_in[4];
    const float* mem_w2  = (const float*)d_in[5];
    const float* alpha_t = (const float*)d_in[6];
    const float* lr_t    = (const float*)d_in[7];
    const float* decay_t = (const float*)d_in[8];
    const int*   upd     = (const int*)d_in[9];
    float* out = (float*)d_out;

    float* sc = nullptr;
    cudaGetSymbolAddress((void**)&sc, g_scratch);
    float* W1  = sc + OFF_W1;   float* W2  = sc + OFF_W2;
    float* W1R = sc + OFF_W1R;  float* W2R = sc + OFF_W2R;
    float* S1  = sc + OFF_S1;   float* S2  = sc + OFF_S2;
    float* HG  = sc + OFF_HG;   float* GP  = sc + OFF_GP;
    float* DH  = sc + OFF_DH;   float* DP  = sc + OFF_DP;
    float* KA  = sc + OFF_KA;   float* VA  = sc + OFF_VA;
    float* Q   = sc + OFF_Q;    float* HQ  = sc + OFF_HQ;
    float* XR  = sc + OFF_XR;
    float* WQR = sc + OFF_WQR;  float* WKR = sc + OFF_WKR;  float* WVR = sc + OFF_WVR;

    // pre-round all external MMA operands
    round_copy<<<8192, 256>>>((const float4*)x,   (float4*)XR,  2097152);
    round_copy<<<256, 256>>>((const float4*)w_q, (float4*)WQR, 65536);
    round_copy<<<256, 256>>>((const float4*)w_k, (float4*)WKR, 65536);
    round_copy<<<256, 256>>>((const float4*)w_v, (float4*)WVR, 65536);
    init_w<<<2048, 256>>>(mem_w1, mem_w2, W1, W1R, S1, W2, W2R, S2);

    Z3P z3 = { WKR, WVR, WQR, KA, VA, Q };
    Z3P z0 = { nullptr, nullptr, nullptr, nullptr, nullptr, nullptr };

    // K_all(rounded)/V_all(fp32) chunk-major + Q(rounded): one launch, grid.z=3
    mgemm<0,0,EPI_NONE,1><<<dim3(8, 256, 3), 128, SMEMSZ>>>(
        XR, nullptr, nullptr, nullptr, nullptr, nullptr, nullptr,
        nullptr, nullptr, nullptr, nullptr, 512, 512, 512, 512, 0, z3);

    for (int c = 0; c < NCHUNK; c++) {
        float* Kc = KA + (size_t)c * 524288;
        float* Vc = VA + (size_t)c * 524288;
        // HG = gelu(Kc @ W1R), GP = gelu'  [1024,1024,512]
        mgemm<0,0,EPI_GELU_BOTH,0><<<dim3(16, 16), 128, SMEMSZ>>>(
            Kc, W1R, HG, GP, nullptr, nullptr, nullptr, nullptr, nullptr, nullptr, nullptr,
            1024, 512, 512, 1024, 0, z0);
        // DP = (HG @ W2R - Vc) * 2/Nel  [1024,512,1024]
        mgemm<0,0,EPI_DPRED,0><<<dim3(8, 16), 128, SMEMSZ>>>(
            HG, W2R, DP, nullptr, nullptr, Vc, nullptr, nullptr, nullptr, nullptr, nullptr,
            512, 1024, 1024, 512, 0, z0);
        // DH = (DP @ W2R^T) * GP  [1024,1024,512]  (B stored [N=1024,K=512] -> TRB)
        mgemm<0,1,EPI_MULGP,0><<<dim3(16, 16), 128, SMEMSZ>>>(
            DP, W2R, DH, nullptr, nullptr, GP, nullptr, nullptr, nullptr, nullptr, nullptr,
            1024, 512, 512, 512, 0, z0);
        // g2 = HG^T @ DP -> update W2/S2/W2R  [M=1024,N=512,K=1024rows]
        mgemm<1,0,EPI_UPDATE,0><<<dim3(8, 16), 128, SMEMSZ>>>(
            HG, DP, W2, nullptr, W2R, nullptr, S2, alpha_t, lr_t, decay_t, upd,
            512, 1024, 1024, 512, 0, z0);
        // g1 = Kc^T @ DH -> update W1/S1/W1R  [M=512,N=1024,K=1024rows]
        mgemm<1,0,EPI_UPDATE,0><<<dim3(16, 8), 128, SMEMSZ>>>(
            Kc, DH, W1, nullptr, W1R, nullptr, S1, alpha_t, lr_t, decay_t, upd,
            1024, 1024, 512, 1024, 0, z0);
    }

    // HQ = gelu(Q @ W1R)  [16384,1024,512]
    mgemm<0,0,EPI_GELU,0><<<dim3(16, 256), 128, SMEMSZ>>>(
        Q, W1R, HQ, nullptr, nullptr, nullptr, nullptr, nullptr, nullptr, nullptr, nullptr,
        1024, 512, 512, 1024, 0, z0);
    // out = HQ @ W2R  [16384,512,1024]  (no rounding on final output)
    mgemm<0,0,EPI_NONE,0><<<dim3(8, 256), 128, SMEMSZ>>>(
        HQ, W2R, out, nullptr, nullptr, nullptr, nullptr, nullptr, nullptr, nullptr, nullptr,
        512, 1024, 1024, 512, 0, z0);
}